// round 3
// baseline (speedup 1.0000x reference)
#include <cuda_runtime.h>

#define B_  2
#define N_  30000
#define C_  32
#define H_  96
#define W_  96
#define D_  96
#define K_  27
#define V_  16
#define TPB 256
#define CS_ (H_*W_*D_)     /* voxels per channel = 884736 */
#define BS_ (C_*CS_)       /* batch stride in (B,C,HWD)   */
#define IK_ (C_*K_)        /* 864 */
#define GPITCH 33          /* smem window pitch [voxel][channel] */

/* smem float offsets */
#define OF_FEAT 0                       /* [16][864]  = 13824 */
#define OF_G    13824                   /* [2][64*33] = 4224  */
#define OF_PART 13824                   /* [8][16][32]= 4096 (overlays OF_G) */
#define OF_SL0  18048                   /* int [16][9] */
#define OF_SL1  18192                   /* int [16][9] */
#define OF_FR   18336                   /* float [16][9] */
#define OF_CX   18480                   /* int [16][4] */
#define OF_CY   18544
#define OF_CZ   18608
#define SMEM_FLOATS 18672
#define SMEM_BYTES  (SMEM_FLOATS*4)     /* 74688 */

__device__ float g_wT[IK_ * C_];                    // wT[ik][o]
__device__ float g_vox2[(size_t)B_ * CS_ * C_];     // channel-last repack, 226MB

__global__ void wt_transpose_kernel(const float* __restrict__ w)
{
    int idx = blockIdx.x * blockDim.x + threadIdx.x;
    if (idx < IK_ * C_) {
        int o = idx % C_;
        int t = idx / C_;
        int i = t / K_;
        int k = t % K_;
        g_wT[idx] = w[(o * C_ + i) * K_ + k];
    }
}

/* (B,C,P) -> (B,P,C), 32x32 smem tiles */
__global__ __launch_bounds__(256)
void vox_transpose_kernel(const float* __restrict__ vox)
{
    __shared__ float t[32][33];
    const int b   = blockIdx.y;
    const size_t p0 = (size_t)blockIdx.x * 32;
    const int lane = threadIdx.x & 31;
    const int row  = threadIdx.x >> 5;          // 0..7
    const float* src = vox + (size_t)b * BS_ + p0;
    #pragma unroll
    for (int rr = 0; rr < 4; ++rr) {
        int c = row + 8 * rr;
        t[c][lane] = __ldg(src + (size_t)c * CS_ + lane);
    }
    __syncthreads();
    float* dst = g_vox2 + ((size_t)b * CS_ + p0) * C_;
    #pragma unroll
    for (int rr = 0; rr < 4; ++rr) {
        int p = row + 8 * rr;
        dst[(size_t)p * C_ + lane] = t[lane][p];
    }
}

__global__ __launch_bounds__(TPB, 3)
void nfs_kernel(const float* __restrict__ verts,
                const float* __restrict__ bias,
                float* __restrict__ out)
{
    extern __shared__ float sm[];
    float* s_feat = sm + OF_FEAT;
    float* s_gb   = sm + OF_G;
    float* s_part = sm + OF_PART;
    int*   s_sl0  = (int*)(sm + OF_SL0);
    int*   s_sl1  = (int*)(sm + OF_SL1);
    float* s_fr   = sm + OF_FR;
    int*   s_cx   = (int*)(sm + OF_CX);
    int*   s_cy   = (int*)(sm + OF_CY);
    int*   s_cz   = (int*)(sm + OF_CZ);

    const int tid = threadIdx.x;
    const int gv0 = blockIdx.x * V_;
    const int b   = gv0 / N_;                  // 30000 % 16 == 0 -> no straddle

    // ---- Phase A: per-vertex per-axis sample math (exact reference order) ----
    if (tid < V_ * 3) {
        const int v = tid / 3, a = tid % 3;    // a: 0->x(D), 1->y(W), 2->z(H)
        const float coord = verts[(gv0 + v) * 3 + a];
        const float sc = (float)(2.0 / (D_ - 1));
        int i0[3], i1[3];
        float fr[3];
        #pragma unroll
        for (int p = 0; p < 3; ++p) {
            float gp = coord + (float)(p - 1) * sc;
            float ip = (gp + 1.0f) * 0.5f * (float)(D_ - 1);
            ip = fminf(fmaxf(ip, 0.0f), (float)(D_ - 1));
            i0[p] = (int)floorf(ip);
            i1[p] = min(i0[p] + 1, D_ - 1);
            fr[p] = ip - (float)i0[p];
        }
        const int wb = i0[1] - 1;              // window base along this axis
        #pragma unroll
        for (int p = 0; p < 3; ++p) {
            s_sl0[v * 9 + a * 3 + p] = min(max(i0[p] - wb, 0), 3);
            s_sl1[v * 9 + a * 3 + p] = min(max(i1[p] - wb, 0), 3);
            s_fr [v * 9 + a * 3 + p] = fr[p];
        }
        #pragma unroll
        for (int j = 0; j < 4; ++j) {
            int cj = min(max(wb + j, 0), D_ - 1);
            if      (a == 0) s_cx[v * 4 + j] = cj;
            else if (a == 1) s_cy[v * 4 + j] = cj * D_;
            else             s_cz[v * 4 + j] = cj * (W_ * D_);
        }
    }
    __syncthreads();

    const float* vbase = g_vox2 + (size_t)b * CS_ * C_;
    const int cb = tid & 31;                   // channel lane
    const int jb = tid >> 5;                   // voxel-slot base (0..7)
    float rg[8];

    // load window for vertex vv into registers (8 coalesced 128B LDGs)
    #define LOADV(vv) {                                                        \
        _Pragma("unroll")                                                      \
        for (int it = 0; it < 8; ++it) {                                       \
            int j = jb + 8 * it;                                               \
            int ro = s_cz[(vv)*4 + (j >> 4)] + s_cy[(vv)*4 + ((j >> 2) & 3)]   \
                   + s_cx[(vv)*4 + (j & 3)];                                   \
            rg[it] = __ldg(vbase + (size_t)ro * C_ + cb);                      \
        } }
    #define STOREV(bf) {                                                       \
        float* dst = s_gb + (bf) * (64 * GPITCH);                              \
        _Pragma("unroll")                                                      \
        for (int it = 0; it < 8; ++it)                                         \
            dst[(jb + 8 * it) * GPITCH + cb] = rg[it];                         \
        }

    LOADV(0); STOREV(0);
    __syncthreads();

    for (int v = 0; v < V_; ++v) {
        const int cur = v & 1;
        if (v + 1 < V_) LOADV(v + 1);          // prefetch overlaps blend below

        // ---- blend 864 (channel,sample) values from smem window ----
        const float* gw = s_gb + cur * (64 * GPITCH);
        for (int t = tid; t < IK_; t += TPB) {
            const int i = t & 31;              // channel (= lane)
            const int k = t >> 5;              // sample (warp-uniform)
            const int p = k / 9, q = (k / 3) % 3, r = k % 3;

            const int sx0 = s_sl0[v*9 + 0*3 + p],      sx1 = s_sl1[v*9 + 0*3 + p];
            const int sy0 = s_sl0[v*9 + 1*3 + q] * 4,  sy1 = s_sl1[v*9 + 1*3 + q] * 4;
            const int sz0 = s_sl0[v*9 + 2*3 + r] * 16, sz1 = s_sl1[v*9 + 2*3 + r] * 16;
            const float fx = s_fr[v*9 + 0*3 + p];
            const float fy = s_fr[v*9 + 1*3 + q];
            const float fz = s_fr[v*9 + 2*3 + r];
            const float gx = 1.0f - fx, gy = 1.0f - fy, gz = 1.0f - fz;

            float acc;
            acc  = gw[(sz0 + sy0 + sx0) * GPITCH + i] * (gz * gy * gx);
            acc += gw[(sz0 + sy0 + sx1) * GPITCH + i] * (gz * gy * fx);
            acc += gw[(sz0 + sy1 + sx0) * GPITCH + i] * (gz * fy * gx);
            acc += gw[(sz0 + sy1 + sx1) * GPITCH + i] * (gz * fy * fx);
            acc += gw[(sz1 + sy0 + sx0) * GPITCH + i] * (fz * gy * gx);
            acc += gw[(sz1 + sy0 + sx1) * GPITCH + i] * (fz * gy * fx);
            acc += gw[(sz1 + sy1 + sx0) * GPITCH + i] * (fz * fy * gx);
            acc += gw[(sz1 + sy1 + sx1) * GPITCH + i] * (fz * fy * fx);
            s_feat[v * IK_ + i * K_ + k] = acc;
        }

        if (v + 1 < V_) STOREV(cur ^ 1);
        __syncthreads();
    }

    // ---- GEMM: out[v][o] = sum_ik feat[v][ik] * wT[ik][o] ----
    {
        const int g    = tid >> 5;             // 8 groups, interleaved ik-chunks of 4
        const int lane = tid & 31;             // o
        float acc[V_];
        #pragma unroll
        for (int v = 0; v < V_; ++v) acc[v] = 0.0f;

        for (int m = 0; m < IK_ / 32; ++m) {   // 27 iterations
            const int t = g * 4 + m * 32;
            const float w0 = g_wT[(t + 0) * C_ + lane];
            const float w1 = g_wT[(t + 1) * C_ + lane];
            const float w2 = g_wT[(t + 2) * C_ + lane];
            const float w3 = g_wT[(t + 3) * C_ + lane];
            #pragma unroll
            for (int v = 0; v < V_; ++v) {
                const float4 f = *(const float4*)&s_feat[v * IK_ + t];
                acc[v] = fmaf(f.x, w0, acc[v]);
                acc[v] = fmaf(f.y, w1, acc[v]);
                acc[v] = fmaf(f.z, w2, acc[v]);
                acc[v] = fmaf(f.w, w3, acc[v]);
            }
        }
        #pragma unroll
        for (int v = 0; v < V_; ++v)
            s_part[(g * V_ + v) * C_ + lane] = acc[v];
    }
    __syncthreads();

    // ---- Final reduce over the 8 groups + bias + store ----
    for (int t = tid; t < V_ * C_; t += TPB) {
        const int v = t >> 5, o = t & 31;
        float r = __ldg(bias + o);
        #pragma unroll
        for (int g = 0; g < 8; ++g) r += s_part[(g * V_ + v) * C_ + o];
        out[(size_t)(gv0 + v) * C_ + o] = r;
    }
}

extern "C" void kernel_launch(void* const* d_in, const int* in_sizes, int n_in,
                              void* d_out, int out_size)
{
    const float* vox   = (const float*)d_in[0];  // (2,32,96,96,96)
    const float* verts = (const float*)d_in[1];  // (2,30000,3)
    const float* cw    = (const float*)d_in[2];  // (32,32,1,27)
    const float* cb    = (const float*)d_in[3];  // (32,)
    float* out = (float*)d_out;                  // (2,30000,32)

    (void)in_sizes; (void)n_in; (void)out_size;

    static int attr_done = 0;
    cudaFuncSetAttribute(nfs_kernel, cudaFuncAttributeMaxDynamicSharedMemorySize,
                         SMEM_BYTES);
    (void)attr_done;

    vox_transpose_kernel<<<dim3(CS_ / 32, B_), 256>>>(vox);
    wt_transpose_kernel<<<(IK_ * C_ + 255) / 256, 256>>>(cw);

    const int nblocks = (B_ * N_) / V_;          // 3750
    nfs_kernel<<<nblocks, TPB, SMEM_BYTES>>>(verts, cb, out);
}

// round 4
// speedup vs baseline: 1.8291x; 1.8291x over previous
#include <cuda_runtime.h>

#define B_  2
#define N_  30000
#define C_  32
#define H_  96
#define W_  96
#define D_  96
#define K_  27
#define V_  8
#define TPB 256
#define CS_ (H_*W_*D_)
#define BS_ (C_*CS_)
#define IK_ (C_*K_)        /* 864 */
#define NT_ (V_*K_)        /* 216 tasks per block */

/* static smem pool (floats):
   [0,6912)            s_feat[8][864]
   [6912,8640)+...     corner tables (reused as s_part during GEMM)      */
#define OF_FEAT 0
#define OF_C    6912                    /* int  [216][8] = 1728 slots */
#define OF_W    8640                    /* float[216][8] = 1728 slots */
#define OF_PART 6912                    /* float[8][8][32] = 2048, overlays OF_C/OF_W */
#define SMEM_FLOATS 10368               /* 41472 B */

__device__ float g_wT[IK_ * C_];                    // wT[k*32+i][o]
__device__ float g_vox2[(size_t)B_ * CS_ * C_];     // channel-last repack

__global__ void wt_transpose_kernel(const float* __restrict__ w)
{
    int idx = blockIdx.x * blockDim.x + threadIdx.x;
    if (idx < IK_ * C_) {
        int o  = idx % C_;
        int rt = idx / C_;             // rt = k*32 + i
        int k  = rt / C_;
        int i  = rt % C_;
        g_wT[idx] = w[(o * C_ + i) * K_ + k];
    }
}

/* (B,C,P) -> (B,P,C), 32x32 smem tiles */
__global__ __launch_bounds__(256)
void vox_transpose_kernel(const float* __restrict__ vox)
{
    __shared__ float t[32][33];
    const int b    = blockIdx.y;
    const size_t p0 = (size_t)blockIdx.x * 32;
    const int lane = threadIdx.x & 31;
    const int row  = threadIdx.x >> 5;
    const float* src = vox + (size_t)b * BS_ + p0;
    #pragma unroll
    for (int rr = 0; rr < 4; ++rr) {
        int c = row + 8 * rr;
        t[c][lane] = __ldg(src + (size_t)c * CS_ + lane);
    }
    __syncthreads();
    float* dst = g_vox2 + ((size_t)b * CS_ + p0) * C_;
    #pragma unroll
    for (int rr = 0; rr < 4; ++rr) {
        int p = row + 8 * rr;
        dst[(size_t)p * C_ + lane] = t[lane][p];
    }
}

__global__ __launch_bounds__(TPB)
void nfs_kernel(const float* __restrict__ verts,
                const float* __restrict__ bias,
                float* __restrict__ out)
{
    __shared__ float sm[SMEM_FLOATS];
    float* s_feat = sm + OF_FEAT;
    int*   s_c    = (int*)(sm + OF_C);
    float* s_w    = sm + OF_W;
    float* s_part = sm + OF_PART;

    const int tid = threadIdx.x;
    const int gv0 = blockIdx.x * V_;
    const int b   = gv0 / N_;                  // N_ % V_ == 0 -> no straddle

    // ---- Phase A: per-(vertex,sample) corner indices + weights (216 tasks) ----
    if (tid < NT_) {
        const int v = tid / K_, k = tid % K_;
        const int gv = gv0 + v;
        const float x = verts[gv * 3 + 0];
        const float y = verts[gv * 3 + 1];
        const float z = verts[gv * 3 + 2];

        const int p = k / 9 - 1;
        const int q = (k / 3) % 3 - 1;
        const int r = k % 3 - 1;
        const float sc = (float)(2.0 / (D_ - 1));

        float ix = (x + (float)p * sc + 1.0f) * 0.5f * (float)(D_ - 1);
        float iy = (y + (float)q * sc + 1.0f) * 0.5f * (float)(W_ - 1);
        float iz = (z + (float)r * sc + 1.0f) * 0.5f * (float)(H_ - 1);
        ix = fminf(fmaxf(ix, 0.0f), (float)(D_ - 1));
        iy = fminf(fmaxf(iy, 0.0f), (float)(W_ - 1));
        iz = fminf(fmaxf(iz, 0.0f), (float)(H_ - 1));

        const int x0 = (int)floorf(ix), y0 = (int)floorf(iy), z0 = (int)floorf(iz);
        const int x1 = min(x0 + 1, D_ - 1);
        const int y1 = min(y0 + 1, W_ - 1);
        const int z1 = min(z0 + 1, H_ - 1);
        const float fx = ix - (float)x0, fy = iy - (float)y0, fz = iz - (float)z0;
        const float gx = 1.0f - fx, gy = 1.0f - fy, gz = 1.0f - fz;

        int*   cc = s_c + tid * 8;
        float* cw = s_w + tid * 8;
        cc[0] = (z0 * W_ + y0) * D_ + x0;  cw[0] = gz * gy * gx;
        cc[1] = (z0 * W_ + y0) * D_ + x1;  cw[1] = gz * gy * fx;
        cc[2] = (z0 * W_ + y1) * D_ + x0;  cw[2] = gz * fy * gx;
        cc[3] = (z0 * W_ + y1) * D_ + x1;  cw[3] = gz * fy * fx;
        cc[4] = (z1 * W_ + y0) * D_ + x0;  cw[4] = fz * gy * gx;
        cc[5] = (z1 * W_ + y0) * D_ + x1;  cw[5] = fz * gy * fx;
        cc[6] = (z1 * W_ + y1) * D_ + x0;  cw[6] = fz * fy * gx;
        cc[7] = (z1 * W_ + y1) * D_ + x1;  cw[7] = fz * fy * fx;
    }
    __syncthreads();

    // ---- Phase B: gather+blend. One warp per (v,k) task, lane = channel. ----
    {
        const float* vbase = g_vox2 + (size_t)b * CS_ * C_;
        const int wid  = tid >> 5;
        const int lane = tid & 31;
        #pragma unroll 3
        for (int t = wid; t < NT_; t += TPB / 32) {
            const int* cc = s_c + t * 8;      // warp-uniform -> LDS broadcast
            const float* cw = s_w + t * 8;
            float f[8];
            #pragma unroll
            for (int j = 0; j < 8; ++j)       // 8 independent 128B LDGs
                f[j] = __ldg(vbase + (size_t)cc[j] * C_ + lane);
            float acc = 0.0f;
            #pragma unroll
            for (int j = 0; j < 8; ++j)
                acc = fmaf(f[j], cw[j], acc);
            const int v = t / K_, k = t % K_;
            s_feat[v * IK_ + k * C_ + lane] = acc;   // contiguous 128B STS
        }
    }
    __syncthreads();

    // ---- GEMM: out[v][o] = sum_rt feat[v][rt] * wT[rt][o],  rt = k*32+i ----
    {
        const int g    = tid >> 5;
        const int lane = tid & 31;
        float acc[V_];
        #pragma unroll
        for (int v = 0; v < V_; ++v) acc[v] = 0.0f;

        for (int m = 0; m < IK_ / 32; ++m) {       // 27 iterations
            const int t = g * 4 + m * 32;
            const float w0 = g_wT[(t + 0) * C_ + lane];
            const float w1 = g_wT[(t + 1) * C_ + lane];
            const float w2 = g_wT[(t + 2) * C_ + lane];
            const float w3 = g_wT[(t + 3) * C_ + lane];
            #pragma unroll
            for (int v = 0; v < V_; ++v) {
                const float4 f = *(const float4*)&s_feat[v * IK_ + t];
                acc[v] = fmaf(f.x, w0, acc[v]);
                acc[v] = fmaf(f.y, w1, acc[v]);
                acc[v] = fmaf(f.z, w2, acc[v]);
                acc[v] = fmaf(f.w, w3, acc[v]);
            }
        }
        __syncthreads();                           // corner tables dead; reuse as s_part
        #pragma unroll
        for (int v = 0; v < V_; ++v)
            s_part[(g * V_ + v) * C_ + lane] = acc[v];
    }
    __syncthreads();

    // ---- Final reduce over 8 groups + bias + store ----
    if (tid < V_ * C_) {
        const int v = tid >> 5, o = tid & 31;
        float r = __ldg(bias + o);
        #pragma unroll
        for (int g = 0; g < 8; ++g) r += s_part[(g * V_ + v) * C_ + o];
        out[(size_t)(gv0 + v) * C_ + o] = r;
    }
}

extern "C" void kernel_launch(void* const* d_in, const int* in_sizes, int n_in,
                              void* d_out, int out_size)
{
    const float* vox   = (const float*)d_in[0];  // (2,32,96,96,96)
    const float* verts = (const float*)d_in[1];  // (2,30000,3)
    const float* cw    = (const float*)d_in[2];  // (32,32,1,27)
    const float* cb    = (const float*)d_in[3];  // (32,)
    float* out = (float*)d_out;                  // (2,30000,32)

    (void)in_sizes; (void)n_in; (void)out_size;

    vox_transpose_kernel<<<dim3(CS_ / 32, B_), 256>>>(vox);
    wt_transpose_kernel<<<(IK_ * C_ + 255) / 256, 256>>>(cw);

    const int nblocks = (B_ * N_) / V_;          // 7500
    nfs_kernel<<<nblocks, TPB>>>(verts, cb, out);
}

// round 5
// speedup vs baseline: 1.8613x; 1.0176x over previous
#include <cuda_runtime.h>

#define B_  2
#define N_  30000
#define C_  32
#define H_  96
#define W_  96
#define D_  96
#define K_  27
#define V_  8
#define TPB 256
#define CS_ (H_*W_*D_)
#define BS_ (C_*CS_)
#define IK_ (C_*K_)        /* 864 */
#define NT_ (V_*K_)        /* 216 tasks per block */

/* static smem pool (floats):
   [0,6912)     s_feat[8][864]
   [6912,..)    corner tables (reused as s_part during GEMM) */
#define OF_FEAT 0
#define OF_C    6912                    /* int  [216][8] = 1728 slots */
#define OF_W    8640                    /* float[216][8] = 1728 slots */
#define OF_PART 6912                    /* float[8][8][32] = 2048 (overlay) */
#define SMEM_FLOATS 10368               /* 41472 B */

__device__ float2 g_wP[(IK_/2) * C_];               // {wT[2tp][o], wT[2tp+1][o]}
__device__ float  g_vox2[(size_t)B_ * CS_ * C_];    // channel-last repack

__device__ __forceinline__ void ffma2(unsigned long long& acc,
                                      unsigned long long a,
                                      unsigned long long b)
{
    asm("fma.rn.f32x2 %0, %1, %2, %0;" : "+l"(acc) : "l"(a), "l"(b));
}

__global__ void wt_pack_kernel(const float* __restrict__ w)
{
    int idx = blockIdx.x * blockDim.x + threadIdx.x;   // pair index * 32 + o
    if (idx < (IK_ / 2) * C_) {
        int o  = idx % C_;
        int tp = idx / C_;
        int rt0 = 2 * tp, rt1 = 2 * tp + 1;            // rt = k*32 + i
        int k0 = rt0 / C_, i0 = rt0 % C_;
        int k1 = rt1 / C_, i1 = rt1 % C_;
        g_wP[idx] = make_float2(w[(o * C_ + i0) * K_ + k0],
                                w[(o * C_ + i1) * K_ + k1]);
    }
}

/* (B,C,P) -> (B,P,C): 32c x 64p tiles, LDG.128 / STG.128 */
__global__ __launch_bounds__(256)
void vox_transpose_kernel(const float* __restrict__ vox)
{
    __shared__ float t[32][65];
    const int b    = blockIdx.y;
    const size_t p0 = (size_t)blockIdx.x * 64;
    const int tid = threadIdx.x;
    {
        const int pv = tid & 15, c0 = tid >> 4;
        const float* src = vox + (size_t)b * BS_ + p0 + 4 * pv;
        #pragma unroll
        for (int h = 0; h < 2; ++h) {
            const int c = c0 + 16 * h;
            const float4 r = *(const float4*)(src + (size_t)c * CS_);
            t[c][4*pv+0] = r.x; t[c][4*pv+1] = r.y;
            t[c][4*pv+2] = r.z; t[c][4*pv+3] = r.w;
        }
    }
    __syncthreads();
    {
        const int cv = tid & 7, p = tid >> 3;          // p 0..31
        float* dst = g_vox2 + ((size_t)b * CS_ + p0) * C_ + 4 * cv;
        #pragma unroll
        for (int h = 0; h < 2; ++h) {
            const int pp = p + 32 * h;
            const float4 r = make_float4(t[4*cv+0][pp], t[4*cv+1][pp],
                                         t[4*cv+2][pp], t[4*cv+3][pp]);
            *(float4*)(dst + (size_t)pp * C_) = r;
        }
    }
}

__global__ __launch_bounds__(TPB)
void nfs_kernel(const float* __restrict__ verts,
                const float* __restrict__ bias,
                float* __restrict__ out)
{
    __shared__ float sm[SMEM_FLOATS];
    float* s_feat = sm + OF_FEAT;
    int*   s_c    = (int*)(sm + OF_C);
    float* s_w    = sm + OF_W;
    float* s_part = sm + OF_PART;

    const int tid = threadIdx.x;
    const int gv0 = blockIdx.x * V_;
    const int b   = gv0 / N_;

    // ---- Phase A: per-(vertex,sample) corner indices + weights ----
    if (tid < NT_) {
        const int v = tid / K_, k = tid % K_;
        const int gv = gv0 + v;
        const float x = verts[gv * 3 + 0];
        const float y = verts[gv * 3 + 1];
        const float z = verts[gv * 3 + 2];

        const int p = k / 9 - 1;
        const int q = (k / 3) % 3 - 1;
        const int r = k % 3 - 1;
        const float sc = (float)(2.0 / (D_ - 1));

        float ix = (x + (float)p * sc + 1.0f) * 0.5f * (float)(D_ - 1);
        float iy = (y + (float)q * sc + 1.0f) * 0.5f * (float)(W_ - 1);
        float iz = (z + (float)r * sc + 1.0f) * 0.5f * (float)(H_ - 1);
        ix = fminf(fmaxf(ix, 0.0f), (float)(D_ - 1));
        iy = fminf(fmaxf(iy, 0.0f), (float)(W_ - 1));
        iz = fminf(fmaxf(iz, 0.0f), (float)(H_ - 1));

        const int x0 = (int)floorf(ix), y0 = (int)floorf(iy), z0 = (int)floorf(iz);
        const int x1 = min(x0 + 1, D_ - 1);
        const int y1 = min(y0 + 1, W_ - 1);
        const int z1 = min(z0 + 1, H_ - 1);
        const float fx = ix - (float)x0, fy = iy - (float)y0, fz = iz - (float)z0;
        const float gx = 1.0f - fx, gy = 1.0f - fy, gz = 1.0f - fz;

        int*   cc = s_c + tid * 8;
        float* cw = s_w + tid * 8;
        cc[0] = (z0 * W_ + y0) * D_ + x0;  cw[0] = gz * gy * gx;
        cc[1] = (z0 * W_ + y0) * D_ + x1;  cw[1] = gz * gy * fx;
        cc[2] = (z0 * W_ + y1) * D_ + x0;  cw[2] = gz * fy * gx;
        cc[3] = (z0 * W_ + y1) * D_ + x1;  cw[3] = gz * fy * fx;
        cc[4] = (z1 * W_ + y0) * D_ + x0;  cw[4] = fz * gy * gx;
        cc[5] = (z1 * W_ + y0) * D_ + x1;  cw[5] = fz * gy * fx;
        cc[6] = (z1 * W_ + y1) * D_ + x0;  cw[6] = fz * fy * gx;
        cc[7] = (z1 * W_ + y1) * D_ + x1;  cw[7] = fz * fy * fx;
    }
    __syncthreads();

    // ---- Phase B: gather+blend. One warp per (v,k); lane = channel. ----
    {
        const float* vbase = g_vox2 + (size_t)b * CS_ * C_;
        const int wid  = tid >> 5;
        const int lane = tid & 31;
        #pragma unroll 3
        for (int t = wid; t < NT_; t += TPB / 32) {
            const int*   cc = s_c + t * 8;     // warp-uniform -> LDS broadcast
            const float* cw = s_w + t * 8;
            float f[8];
            #pragma unroll
            for (int j = 0; j < 8; ++j)        // 8 independent 128B LDGs
                f[j] = __ldg(vbase + (size_t)cc[j] * C_ + lane);
            float acc = 0.0f;
            #pragma unroll
            for (int j = 0; j < 8; ++j)
                acc = fmaf(f[j], cw[j], acc);
            const int v = t / K_, k = t % K_;
            s_feat[v * IK_ + k * C_ + lane] = acc;
        }
    }
    __syncthreads();

    // ---- GEMM with packed f32x2 FMAs: rt = k*32+i ----
    {
        const int g    = tid >> 5;
        const int lane = tid & 31;
        unsigned long long acc[V_];
        #pragma unroll
        for (int v = 0; v < V_; ++v) acc[v] = 0ull;

        for (int m = 0; m < IK_ / 32; ++m) {            // 27 iterations
            const int t0 = g * 4 + m * 32;              // multiple of 4
            const int tp = t0 >> 1;
            const unsigned long long w01 =
                *(const unsigned long long*)&g_wP[tp * C_ + lane];
            const unsigned long long w23 =
                *(const unsigned long long*)&g_wP[(tp + 1) * C_ + lane];
            #pragma unroll
            for (int v = 0; v < V_; ++v) {
                const ulonglong2 f =
                    *(const ulonglong2*)&s_feat[v * IK_ + t0];  // 16B aligned
                ffma2(acc[v], f.x, w01);
                ffma2(acc[v], f.y, w23);
            }
        }
        __syncthreads();                    // corner tables dead; reuse as s_part
        #pragma unroll
        for (int v = 0; v < V_; ++v) {
            float lo, hi;
            asm("mov.b64 {%0,%1}, %2;" : "=f"(lo), "=f"(hi) : "l"(acc[v]));
            s_part[(g * V_ + v) * C_ + lane] = lo + hi;
        }
    }
    __syncthreads();

    // ---- Final reduce over 8 groups + bias + store ----
    if (tid < V_ * C_) {
        const int v = tid >> 5, o = tid & 31;
        float r = __ldg(bias + o);
        #pragma unroll
        for (int g = 0; g < 8; ++g) r += s_part[(g * V_ + v) * C_ + o];
        out[(size_t)(gv0 + v) * C_ + o] = r;
    }
}

extern "C" void kernel_launch(void* const* d_in, const int* in_sizes, int n_in,
                              void* d_out, int out_size)
{
    const float* vox   = (const float*)d_in[0];  // (2,32,96,96,96)
    const float* verts = (const float*)d_in[1];  // (2,30000,3)
    const float* cw    = (const float*)d_in[2];  // (32,32,1,27)
    const float* cb    = (const float*)d_in[3];  // (32,)
    float* out = (float*)d_out;                  // (2,30000,32)

    (void)in_sizes; (void)n_in; (void)out_size;

    vox_transpose_kernel<<<dim3(CS_ / 64, B_), 256>>>(vox);
    wt_pack_kernel<<<((IK_ / 2) * C_ + 255) / 256, 256>>>(cw);

    const int nblocks = (B_ * N_) / V_;          // 7500
    nfs_kernel<<<nblocks, TPB>>>(verts, cb, out);
}

// round 6
// speedup vs baseline: 2.0084x; 1.0790x over previous
#include <cuda_runtime.h>

#define B_  2
#define N_  30000
#define C_  32
#define H_  96
#define W_  96
#define D_  96
#define K_  27
#define V_  8
#define TPB 256
#define CS_ (H_*W_*D_)
#define BS_ (C_*CS_)
#define IK_ (C_*K_)        /* 864 */
#define NT_ (V_*K_)        /* 216 */

/* dynamic smem layout (float offsets) */
#define OF_FEAT 0                 /* [8][864]            6912  */
#define OF_WIN  6912              /* [4][64][32]         8192  */
#define OF_PART 6912              /* [8][8][32] overlay  2048  */
#define OF_CC   15104             /* short[216][8]        864  */
#define OF_CW   15968             /* float[216][8]       1728  */
#define OF_RO   17696             /* int[8][64]           512  */
#define OF_SL0  18208             /* int[8][3][3]          72  */
#define OF_SL1  18280             /*                       72  */
#define OF_FR   18352             /* float                 72  */
#define OF_CX   18424             /* int[8][4]             32  */
#define OF_CY   18456             /*                       32  */
#define OF_CZ   18488             /*                       32  */
#define SMEM_FLOATS 18520
#define SMEM_BYTES  (SMEM_FLOATS*4)   /* 74080 */

struct alignas(16) S8 { short s[8]; };

__device__ float2 g_wP[(IK_/2) * C_];               // packed weight pairs
__device__ float  g_vox2[(size_t)B_ * CS_ * C_];    // channel-last repack

__device__ __forceinline__ void ffma2(unsigned long long& acc,
                                      unsigned long long a,
                                      unsigned long long b)
{
    asm("fma.rn.f32x2 %0, %1, %2, %0;" : "+l"(acc) : "l"(a), "l"(b));
}

__global__ void wt_pack_kernel(const float* __restrict__ w)
{
    int idx = blockIdx.x * blockDim.x + threadIdx.x;
    if (idx < (IK_ / 2) * C_) {
        int o  = idx % C_;
        int tp = idx / C_;
        int rt0 = 2 * tp, rt1 = 2 * tp + 1;            // rt = k*32 + i
        int k0 = rt0 / C_, i0 = rt0 % C_;
        int k1 = rt1 / C_, i1 = rt1 % C_;
        g_wP[idx] = make_float2(w[(o * C_ + i0) * K_ + k0],
                                w[(o * C_ + i1) * K_ + k1]);
    }
}

/* (B,C,P) -> (B,P,C): 32c x 64p tiles, LDG.128 / STG.128 */
__global__ __launch_bounds__(256)
void vox_transpose_kernel(const float* __restrict__ vox)
{
    __shared__ float t[32][65];
    const int b    = blockIdx.y;
    const size_t p0 = (size_t)blockIdx.x * 64;
    const int tid = threadIdx.x;
    {
        const int pv = tid & 15, c0 = tid >> 4;
        const float* src = vox + (size_t)b * BS_ + p0 + 4 * pv;
        #pragma unroll
        for (int h = 0; h < 2; ++h) {
            const int c = c0 + 16 * h;
            const float4 r = *(const float4*)(src + (size_t)c * CS_);
            t[c][4*pv+0] = r.x; t[c][4*pv+1] = r.y;
            t[c][4*pv+2] = r.z; t[c][4*pv+3] = r.w;
        }
    }
    __syncthreads();
    {
        const int cv = tid & 7, p = tid >> 3;
        float* dst = g_vox2 + ((size_t)b * CS_ + p0) * C_ + 4 * cv;
        #pragma unroll
        for (int h = 0; h < 2; ++h) {
            const int pp = p + 32 * h;
            const float4 r = make_float4(t[4*cv+0][pp], t[4*cv+1][pp],
                                         t[4*cv+2][pp], t[4*cv+3][pp]);
            *(float4*)(dst + (size_t)pp * C_) = r;
        }
    }
}

__global__ __launch_bounds__(TPB, 3)
void nfs_kernel(const float* __restrict__ verts,
                const float* __restrict__ bias,
                float* __restrict__ out)
{
    extern __shared__ float sm[];
    float* s_feat = sm + OF_FEAT;
    float* s_win  = sm + OF_WIN;
    float* s_part = sm + OF_PART;
    short* s_cc   = (short*)(sm + OF_CC);
    float* s_cw   = sm + OF_CW;
    int*   s_ro   = (int*)(sm + OF_RO);
    int*   s_sl0  = (int*)(sm + OF_SL0);
    int*   s_sl1  = (int*)(sm + OF_SL1);
    float* s_fr   = sm + OF_FR;
    int*   s_cx   = (int*)(sm + OF_CX);
    int*   s_cy   = (int*)(sm + OF_CY);
    int*   s_cz   = (int*)(sm + OF_CZ);

    const int tid  = threadIdx.x;
    const int w    = tid >> 5;
    const int lane = tid & 31;
    const int gv0  = blockIdx.x * V_;
    const int b    = gv0 / N_;

    // ---- Phase A1: per-(vertex,axis) slots/fractions/window coords ----
    if (tid < V_ * 3) {
        const int v = tid / 3, a = tid % 3;        // a: 0->x(D), 1->y(W), 2->z(H)
        const float coord = verts[(gv0 + v) * 3 + a];
        const float sc = (float)(2.0 / (D_ - 1));
        int i0[3], i1[3];
        float fr[3];
        #pragma unroll
        for (int p = 0; p < 3; ++p) {
            float gp = coord + (float)(p - 1) * sc;
            float ip = (gp + 1.0f) * 0.5f * (float)(D_ - 1);
            ip = fminf(fmaxf(ip, 0.0f), (float)(D_ - 1));
            i0[p] = (int)floorf(ip);
            i1[p] = min(i0[p] + 1, D_ - 1);
            fr[p] = ip - (float)i0[p];
        }
        const int wb = i0[1] - 1;
        #pragma unroll
        for (int p = 0; p < 3; ++p) {
            s_sl0[v * 9 + a * 3 + p] = min(max(i0[p] - wb, 0), 3);
            s_sl1[v * 9 + a * 3 + p] = min(max(i1[p] - wb, 0), 3);
            s_fr [v * 9 + a * 3 + p] = fr[p];
        }
        #pragma unroll
        for (int j = 0; j < 4; ++j) {
            int cj = min(max(wb + j, 0), D_ - 1);
            if      (a == 0) s_cx[v * 4 + j] = cj;
            else if (a == 1) s_cy[v * 4 + j] = cj * D_;
            else             s_cz[v * 4 + j] = cj * (W_ * D_);
        }
    }
    __syncthreads();

    // ---- Phase A2: pack per-task corner slot-offsets + weights; window addrs ----
    if (tid < NT_) {
        const int v = tid / K_, k = tid % K_;
        const int p = k / 9, q = (k / 3) % 3, r = k % 3;
        const int sx0 = s_sl0[v*9 + 0*3 + p],       sx1 = s_sl1[v*9 + 0*3 + p];
        const int sy0 = s_sl0[v*9 + 1*3 + q] * 4,   sy1 = s_sl1[v*9 + 1*3 + q] * 4;
        const int sz0 = s_sl0[v*9 + 2*3 + r] * 16,  sz1 = s_sl1[v*9 + 2*3 + r] * 16;
        const float fx = s_fr[v*9 + 0*3 + p];
        const float fy = s_fr[v*9 + 1*3 + q];
        const float fz = s_fr[v*9 + 2*3 + r];
        const float gx = 1.0f - fx, gy = 1.0f - fy, gz = 1.0f - fz;

        short* cc = s_cc + tid * 8;                 // slot offsets premultiplied by 32
        float* cw = s_cw + tid * 8;
        cc[0] = (short)((sz0 + sy0 + sx0) * 32);  cw[0] = gz * gy * gx;
        cc[1] = (short)((sz0 + sy0 + sx1) * 32);  cw[1] = gz * gy * fx;
        cc[2] = (short)((sz0 + sy1 + sx0) * 32);  cw[2] = gz * fy * gx;
        cc[3] = (short)((sz0 + sy1 + sx1) * 32);  cw[3] = gz * fy * fx;
        cc[4] = (short)((sz1 + sy0 + sx0) * 32);  cw[4] = fz * gy * gx;
        cc[5] = (short)((sz1 + sy0 + sx1) * 32);  cw[5] = fz * gy * fx;
        cc[6] = (short)((sz1 + sy1 + sx0) * 32);  cw[6] = fz * fy * gx;
        cc[7] = (short)((sz1 + sy1 + sx1) * 32);  cw[7] = fz * fy * fx;
    }
    #pragma unroll
    for (int idx = tid; idx < V_ * 64; idx += TPB) {   // global row offsets per window slot
        const int v = idx >> 6, j = idx & 63;
        s_ro[idx] = s_cz[v*4 + (j >> 4)] + s_cy[v*4 + ((j >> 2) & 3)]
                  + s_cx[v*4 + (j & 3)];
    }
    __syncthreads();

    // ---- Phase B: per half (4 vertices): cooperative window gather, then blend ----
    const float* vbase = g_vox2 + (size_t)b * CS_ * C_;
    for (int h = 0; h < 2; ++h) {
        const int v  = 4 * h + (w >> 1);
        const int jb = (w & 1) * 32;
        float* winv = s_win + (v & 3) * 2048;
        #pragma unroll
        for (int ch = 0; ch < 2; ++ch) {               // 2 chunks of 16 (MLP=16)
            float tmp[16];
            #pragma unroll
            for (int s = 0; s < 16; ++s) {
                const int j = jb + ch * 16 + s;
                tmp[s] = __ldg(vbase + (size_t)s_ro[(v << 6) | j] * C_ + lane);
            }
            #pragma unroll
            for (int s = 0; s < 16; ++s)
                winv[(jb + ch * 16 + s) * 32 + lane] = tmp[s];
        }
        __syncthreads();

        // blend 4*27 = 108 tasks over 8 warps; lane = channel
        for (int t = w; t < 4 * K_; t += 8) {
            const int vloc = t / K_, k = t % K_;
            const int vv = 4 * h + vloc;
            const int tg = vv * K_ + k;
            const S8 cc = ((const S8*)s_cc)[tg];
            const float4 wA = ((const float4*)s_cw)[tg * 2];
            const float4 wB = ((const float4*)s_cw)[tg * 2 + 1];
            const float* wv = s_win + vloc * 2048 + lane;
            float acc;
            acc  = wv[cc.s[0]] * wA.x;
            acc += wv[cc.s[1]] * wA.y;
            acc += wv[cc.s[2]] * wA.z;
            acc += wv[cc.s[3]] * wA.w;
            acc += wv[cc.s[4]] * wB.x;
            acc += wv[cc.s[5]] * wB.y;
            acc += wv[cc.s[6]] * wB.z;
            acc += wv[cc.s[7]] * wB.w;
            s_feat[vv * IK_ + k * C_ + lane] = acc;
        }
        __syncthreads();
    }

    // ---- GEMM with packed f32x2 FMAs: rt = k*32+i ----
    {
        unsigned long long acc[V_];
        #pragma unroll
        for (int v = 0; v < V_; ++v) acc[v] = 0ull;

        for (int m = 0; m < IK_ / 32; ++m) {           // 27 iterations
            const int t0 = w * 4 + m * 32;
            const int tp = t0 >> 1;
            const unsigned long long w01 =
                *(const unsigned long long*)&g_wP[tp * C_ + lane];
            const unsigned long long w23 =
                *(const unsigned long long*)&g_wP[(tp + 1) * C_ + lane];
            #pragma unroll
            for (int v = 0; v < V_; ++v) {
                const ulonglong2 f =
                    *(const ulonglong2*)&s_feat[v * IK_ + t0];
                ffma2(acc[v], f.x, w01);
                ffma2(acc[v], f.y, w23);
            }
        }
        __syncthreads();                // s_win dead; reuse as s_part
        #pragma unroll
        for (int v = 0; v < V_; ++v) {
            float lo, hi;
            asm("mov.b64 {%0,%1}, %2;" : "=f"(lo), "=f"(hi) : "l"(acc[v]));
            s_part[(w * V_ + v) * C_ + lane] = lo + hi;
        }
    }
    __syncthreads();

    // ---- Final reduce over 8 groups + bias + store ----
    if (tid < V_ * C_) {
        const int v = tid >> 5, o = tid & 31;
        float r = __ldg(bias + o);
        #pragma unroll
        for (int g = 0; g < 8; ++g) r += s_part[(g * V_ + v) * C_ + o];
        out[(size_t)(gv0 + v) * C_ + o] = r;
    }
}

extern "C" void kernel_launch(void* const* d_in, const int* in_sizes, int n_in,
                              void* d_out, int out_size)
{
    const float* vox   = (const float*)d_in[0];  // (2,32,96,96,96)
    const float* verts = (const float*)d_in[1];  // (2,30000,3)
    const float* cw    = (const float*)d_in[2];  // (32,32,1,27)
    const float* cb    = (const float*)d_in[3];  // (32,)
    float* out = (float*)d_out;                  // (2,30000,32)

    (void)in_sizes; (void)n_in; (void)out_size;

    cudaFuncSetAttribute(nfs_kernel, cudaFuncAttributeMaxDynamicSharedMemorySize,
                         SMEM_BYTES);

    vox_transpose_kernel<<<dim3(CS_ / 64, B_), 256>>>(vox);
    wt_pack_kernel<<<((IK_ / 2) * C_ + 255) / 256, 256>>>(cw);

    const int nblocks = (B_ * N_) / V_;          // 7500
    nfs_kernel<<<nblocks, TPB, SMEM_BYTES>>>(verts, cb, out);
}

// round 8
// speedup vs baseline: 2.0908x; 1.0410x over previous
#include <cuda_runtime.h>

#define B_  2
#define N_  30000
#define C_  32
#define H_  96
#define W_  96
#define D_  96
#define K_  27
#define V_  8
#define TPB 256
#define CS_ (H_*W_*D_)
#define BS_ (C_*CS_)
#define IK_ (C_*K_)        /* 864 */
#define NT_ (V_*K_)        /* 216 */

/* dynamic smem layout (float offsets) */
#define OF_FEAT 0                 /* [8][864]                 6912 */
#define OF_WIN  6912              /* [2][64][32]              4096 */
#define OF_PART 6912              /* [8][8][32] overlay       2048 */
#define OF_CC   11008             /* short[216][8]             864 */
#define OF_CW   11872             /* float[216][8]            1728 */
#define OF_WB   13600             /* int[8][3]                  24 */
#define SMEM_FLOATS 13632
#define SMEM_BYTES  (SMEM_FLOATS*4)   /* 54528 -> 4 blocks/SM */

struct alignas(16) S8 { short s[8]; };

__device__ float2 g_wP[(IK_/2) * C_];                        // packed weight pairs
__device__ __align__(128) float g_vox2[(size_t)B_ * CS_ * C_];  // channel-last

__device__ __forceinline__ void ffma2(unsigned long long& acc,
                                      unsigned long long a,
                                      unsigned long long b)
{
    asm("fma.rn.f32x2 %0, %1, %2, %0;" : "+l"(acc) : "l"(a), "l"(b));
}

__global__ void wt_pack_kernel(const float* __restrict__ w)
{
    int idx = blockIdx.x * blockDim.x + threadIdx.x;
    if (idx < (IK_ / 2) * C_) {
        int o  = idx % C_;
        int tp = idx / C_;
        int rt0 = 2 * tp, rt1 = 2 * tp + 1;            // rt = k*32 + i
        int k0 = rt0 / C_, i0 = rt0 % C_;
        int k1 = rt1 / C_, i1 = rt1 % C_;
        g_wP[idx] = make_float2(w[(o * C_ + i0) * K_ + k0],
                                w[(o * C_ + i1) * K_ + k1]);
    }
}

/* (B,C,P) -> (B,P,C): 32c x 64p tiles, LDG.128 / STG.128 */
__global__ __launch_bounds__(256)
void vox_transpose_kernel(const float* __restrict__ vox)
{
    __shared__ float t[32][65];
    const int b    = blockIdx.y;
    const size_t p0 = (size_t)blockIdx.x * 64;
    const int tid = threadIdx.x;
    {
        const int pv = tid & 15, c0 = tid >> 4;
        const float* src = vox + (size_t)b * BS_ + p0 + 4 * pv;
        #pragma unroll
        for (int h = 0; h < 2; ++h) {
            const int c = c0 + 16 * h;
            const float4 r = *(const float4*)(src + (size_t)c * CS_);
            t[c][4*pv+0] = r.x; t[c][4*pv+1] = r.y;
            t[c][4*pv+2] = r.z; t[c][4*pv+3] = r.w;
        }
    }
    __syncthreads();
    {
        const int cv = tid & 7, p = tid >> 3;
        float* dst = g_vox2 + ((size_t)b * CS_ + p0) * C_ + 4 * cv;
        #pragma unroll
        for (int h = 0; h < 2; ++h) {
            const int pp = p + 32 * h;
            const float4 r = make_float4(t[4*cv+0][pp], t[4*cv+1][pp],
                                         t[4*cv+2][pp], t[4*cv+3][pp]);
            *(float4*)(dst + (size_t)pp * C_) = r;
        }
    }
}

__global__ __launch_bounds__(TPB, 4)
void nfs_kernel(const float* __restrict__ verts,
                const float* __restrict__ bias,
                float* __restrict__ out)
{
    extern __shared__ float sm[];
    float* s_feat = sm + OF_FEAT;
    float* s_win  = sm + OF_WIN;
    float* s_part = sm + OF_PART;
    short* s_cc   = (short*)(sm + OF_CC);
    float* s_cw   = sm + OF_CW;
    int*   s_wb   = (int*)(sm + OF_WB);

    const int tid  = threadIdx.x;
    const int w    = tid >> 5;
    const int lane = tid & 31;
    const int gv0  = blockIdx.x * V_;
    const int b    = gv0 / N_;

    // ---- Phase A: per-(vertex,sample) slot offsets + trilinear weights ----
    if (tid < NT_) {
        const int v = tid / K_, k = tid % K_;
        const int gv = gv0 + v;
        const float x = verts[gv * 3 + 0];
        const float y = verts[gv * 3 + 1];
        const float z = verts[gv * 3 + 2];

        const int p = k / 9 - 1;
        const int q = (k / 3) % 3 - 1;
        const int r = k % 3 - 1;
        const float sc = (float)(2.0 / (D_ - 1));

        // this task's sample (exact reference arithmetic order)
        float ix = (x + (float)p * sc + 1.0f) * 0.5f * (float)(D_ - 1);
        float iy = (y + (float)q * sc + 1.0f) * 0.5f * (float)(W_ - 1);
        float iz = (z + (float)r * sc + 1.0f) * 0.5f * (float)(H_ - 1);
        ix = fminf(fmaxf(ix, 0.0f), (float)(D_ - 1));
        iy = fminf(fmaxf(iy, 0.0f), (float)(W_ - 1));
        iz = fminf(fmaxf(iz, 0.0f), (float)(H_ - 1));
        const int x0 = (int)floorf(ix), y0 = (int)floorf(iy), z0 = (int)floorf(iz);
        const int x1 = min(x0 + 1, D_ - 1);
        const int y1 = min(y0 + 1, W_ - 1);
        const int z1 = min(z0 + 1, H_ - 1);
        const float fx = ix - (float)x0, fy = iy - (float)y0, fz = iz - (float)z0;
        const float gx = 1.0f - fx, gy = 1.0f - fy, gz = 1.0f - fz;

        // window base from the center sample (identical for all 27 tasks of v)
        float cxp = (x + 1.0f) * 0.5f * (float)(D_ - 1);
        float cyp = (y + 1.0f) * 0.5f * (float)(W_ - 1);
        float czp = (z + 1.0f) * 0.5f * (float)(H_ - 1);
        cxp = fminf(fmaxf(cxp, 0.0f), (float)(D_ - 1));
        cyp = fminf(fmaxf(cyp, 0.0f), (float)(W_ - 1));
        czp = fminf(fmaxf(czp, 0.0f), (float)(H_ - 1));
        const int wbx = (int)floorf(cxp) - 1;
        const int wby = (int)floorf(cyp) - 1;
        const int wbz = (int)floorf(czp) - 1;
        if (k == 0) {
            s_wb[v * 3 + 0] = wbx;
            s_wb[v * 3 + 1] = wby;
            s_wb[v * 3 + 2] = wbz;
        }

        const int sx0 = min(max(x0 - wbx, 0), 3),      sx1 = min(max(x1 - wbx, 0), 3);
        const int sy0 = min(max(y0 - wby, 0), 3) * 4,  sy1 = min(max(y1 - wby, 0), 3) * 4;
        const int sz0 = min(max(z0 - wbz, 0), 3) * 16, sz1 = min(max(z1 - wbz, 0), 3) * 16;

        short* cc = s_cc + tid * 8;        // slot offsets premultiplied by 32
        float* cw = s_cw + tid * 8;
        cc[0] = (short)((sz0 + sy0 + sx0) * 32);  cw[0] = gz * gy * gx;
        cc[1] = (short)((sz0 + sy0 + sx1) * 32);  cw[1] = gz * gy * fx;
        cc[2] = (short)((sz0 + sy1 + sx0) * 32);  cw[2] = gz * fy * gx;
        cc[3] = (short)((sz0 + sy1 + sx1) * 32);  cw[3] = gz * fy * fx;
        cc[4] = (short)((sz1 + sy0 + sx0) * 32);  cw[4] = fz * gy * gx;
        cc[5] = (short)((sz1 + sy0 + sx1) * 32);  cw[5] = fz * gy * fx;
        cc[6] = (short)((sz1 + sy1 + sx0) * 32);  cw[6] = fz * fy * gx;
        cc[7] = (short)((sz1 + sy1 + sx1) * 32);  cw[7] = fz * fy * fx;
    }
    __syncthreads();

    // ---- Phase B: 4 phases x 2 vertices: vectorized window gather, then blend ----
    const float* vbase = g_vox2 + (size_t)b * CS_ * C_;
    for (int h = 0; h < 4; ++h) {
        const int v    = 2 * h + (w >> 2);     // 4 warps per vertex
        const int jb   = (w & 3) * 16;         // 16 rows per warp
        const int r4   = lane >> 3;            // row within quad
        const int cq   = lane & 7;             // channel quad
        const int wbx  = s_wb[v * 3 + 0];
        const int wby  = s_wb[v * 3 + 1];
        const int wbz  = s_wb[v * 3 + 2];
        float* winv = s_win + (v & 1) * 2048;

        float4 tmp[4];
        #pragma unroll
        for (int it = 0; it < 4; ++it) {       // 4 LDG.128 per warp (16 rows)
            const int j  = jb + it * 4 + r4;
            const int cx = min(max(wbx + (j & 3), 0), D_ - 1);
            const int cy = min(max(wby + ((j >> 2) & 3), 0), W_ - 1);
            const int cz = min(max(wbz + (j >> 4), 0), H_ - 1);
            const int ro = (cz * W_ + cy) * D_ + cx;
            tmp[it] = *(const float4*)(vbase + (size_t)ro * C_ + cq * 4);
        }
        #pragma unroll
        for (int it = 0; it < 4; ++it) {       // 4 STS.128
            const int j = jb + it * 4 + r4;
            *(float4*)(winv + j * 32 + cq * 4) = tmp[it];
        }
        __syncthreads();

        // blend 2*27 = 54 tasks over 8 warps; lane = channel
        for (int t = w; t < 2 * K_; t += 8) {
            const int vloc = t / K_, k = t % K_;
            const int vv = 2 * h + vloc;
            const int tg = vv * K_ + k;
            const S8 cc = ((const S8*)s_cc)[tg];
            const float4 wA = ((const float4*)s_cw)[tg * 2];
            const float4 wB = ((const float4*)s_cw)[tg * 2 + 1];
            const float* wv = s_win + vloc * 2048 + lane;
            float acc;
            acc  = wv[cc.s[0]] * wA.x;
            acc += wv[cc.s[1]] * wA.y;
            acc += wv[cc.s[2]] * wA.z;
            acc += wv[cc.s[3]] * wA.w;
            acc += wv[cc.s[4]] * wB.x;
            acc += wv[cc.s[5]] * wB.y;
            acc += wv[cc.s[6]] * wB.z;
            acc += wv[cc.s[7]] * wB.w;
            s_feat[vv * IK_ + k * C_ + lane] = acc;
        }
        __syncthreads();
    }

    // ---- GEMM with packed f32x2 FMAs: rt = k*32+i ----
    {
        unsigned long long acc[V_];
        #pragma unroll
        for (int v = 0; v < V_; ++v) acc[v] = 0ull;

        for (int m = 0; m < IK_ / 32; ++m) {           // 27 iterations
            const int t0 = w * 4 + m * 32;
            const int tp = t0 >> 1;
            const unsigned long long w01 =
                *(const unsigned long long*)&g_wP[tp * C_ + lane];
            const unsigned long long w23 =
                *(const unsigned long long*)&g_wP[(tp + 1) * C_ + lane];
            #pragma unroll
            for (int v = 0; v < V_; ++v) {
                const ulonglong2 f =
                    *(const ulonglong2*)&s_feat[v * IK_ + t0];
                ffma2(acc[v], f.x, w01);
                ffma2(acc[v], f.y, w23);
            }
        }
        __syncthreads();                // s_win dead; reuse as s_part
        #pragma unroll
        for (int v = 0; v < V_; ++v) {
            float lo, hi;
            asm("mov.b64 {%0,%1}, %2;" : "=f"(lo), "=f"(hi) : "l"(acc[v]));
            s_part[(w * V_ + v) * C_ + lane] = lo + hi;
        }
    }
    __syncthreads();

    // ---- Final reduce over 8 groups + bias + store ----
    if (tid < V_ * C_) {
        const int v = tid >> 5, o = tid & 31;
        float r = __ldg(bias + o);
        #pragma unroll
        for (int g = 0; g < 8; ++g) r += s_part[(g * V_ + v) * C_ + o];
        out[(size_t)(gv0 + v) * C_ + o] = r;
    }
}

extern "C" void kernel_launch(void* const* d_in, const int* in_sizes, int n_in,
                              void* d_out, int out_size)
{
    const float* vox   = (const float*)d_in[0];  // (2,32,96,96,96)
    const float* verts = (const float*)d_in[1];  // (2,30000,3)
    const float* cw    = (const float*)d_in[2];  // (32,32,1,27)
    const float* cb    = (const float*)d_in[3];  // (32,)
    float* out = (float*)d_out;                  // (2,30000,32)

    (void)in_sizes; (void)n_in; (void)out_size;

    cudaFuncSetAttribute(nfs_kernel, cudaFuncAttributeMaxDynamicSharedMemorySize,
                         SMEM_BYTES);

    vox_transpose_kernel<<<dim3(CS_ / 64, B_), 256>>>(vox);
    wt_pack_kernel<<<((IK_ / 2) * C_ + 255) / 256, 256>>>(cw);

    const int nblocks = (B_ * N_) / V_;          // 7500
    nfs_kernel<<<nblocks, TPB, SMEM_BYTES>>>(verts, cb, out);
}